// round 7
// baseline (speedup 1.0000x reference)
#include <cuda_runtime.h>
#include <math.h>

// Problem constants
#define NNODES 10000
#define NEDGE  160000
#define NET    170000      // edges + self loops
#define FIN    128
#define HID    512
#define NH     8
#define CHC    64
#define NCLS   10
#define NLAY   3

// ---------------- scratch (no allocation allowed) ----------------
__device__ float g_h  [NNODES * HID];
__device__ float g_o  [NNODES * HID];
__device__ float g_xl [NNODES * HID];
__device__ float g_xr [NNODES * HID];
__device__ int   g_deg [NNODES];
__device__ int   g_off [NNODES + 1];
__device__ int   g_slot[NNODES];
__device__ int   g_csrc[NET];
__device__ float g_cdist[NET];
__device__ int   g_is64;

__device__ __forceinline__ float elu_fast(float v) {
    return v > 0.f ? v : (__expf(v) - 1.f);
}

// ---------------- dtype detect + zero (fused) ----------------
// jax default disables x64, so jnp.int64 may actually be int32. Detect on
// device: int64 values in [0, 2^31) have zero high 32-bit words. If the data
// were int32, the sampled odd words are random node IDs; all-32-zero has
// probability ~1e-128.
__global__ void k_init(const int* ei_raw) {
    int i = blockIdx.x * blockDim.x + threadIdx.x;
    if (i < NNODES) { g_deg[i] = 0; g_slot[i] = 0; }
    if (i == 0) {
        int all_zero = 1;
        for (int j = 1; j < 64; j += 2)
            if (ei_raw[j] != 0) { all_zero = 0; break; }
        g_is64 = all_zero;
    }
}

__device__ __forceinline__ int edge_val(const void* ei, int idx) {
    if (g_is64) return (int)(((const long long*)ei)[idx]);
    return ((const int*)ei)[idx];
}

// ---------------- CSR build (edges grouped by dst) ----------------
__global__ void k_count(const void* ei) {
    int e = blockIdx.x * blockDim.x + threadIdx.x;
    if (e >= NET) return;
    int dst = (e < NEDGE) ? edge_val(ei, NEDGE + e) : (e - NEDGE);
    atomicAdd(&g_deg[dst], 1);
}

__global__ void k_scan() {
    __shared__ int part[1024];
    const int PER = (NNODES + 1023) / 1024;   // 10
    int tid = threadIdx.x;
    int base = tid * PER;
    int s = 0;
    for (int i = 0; i < PER; i++) {
        int idx = base + i;
        if (idx < NNODES) s += g_deg[idx];
    }
    part[tid] = s;
    __syncthreads();
    for (int off = 1; off < 1024; off <<= 1) {
        int v = (tid >= off) ? part[tid - off] : 0;
        __syncthreads();
        part[tid] += v;
        __syncthreads();
    }
    int run = (tid == 0) ? 0 : part[tid - 1];
    for (int i = 0; i < PER; i++) {
        int idx = base + i;
        if (idx < NNODES) { g_off[idx] = run; run += g_deg[idx]; }
    }
    if (tid == 0) g_off[NNODES] = part[1023];
}

__global__ void k_scatter(const void* ei, const float* __restrict__ dist) {
    int e = blockIdx.x * blockDim.x + threadIdx.x;
    if (e >= NET) return;
    int src, dst; float dv;
    if (e < NEDGE) {
        src = edge_val(ei, e);
        dst = edge_val(ei, NEDGE + e);
        dv  = dist[e];
    } else {
        src = dst = e - NEDGE;
        dv = 0.0f;   // FILL
    }
    int pos = g_off[dst] + atomicAdd(&g_slot[dst], 1);
    g_csrc[pos] = src;
    g_cdist[pos] = dv;
}

#define BM 128
#define BN 64
#define BK 16

// ---------------- tiled fp32 GEMM: C = act(A @ B + bias) ----------------
// 128x64 tile, 256 threads, 8x4 microtile, double-buffered smem.
__global__ void __launch_bounds__(256, 2)
k_gemm(const float* __restrict__ A, const float* __restrict__ B,
       const float* __restrict__ bias, float* __restrict__ C,
       int M, int K, int Ncols, int act) {
    __shared__ float As[2][BK][BM + 4];
    __shared__ float Bs[2][BK][BN];
    int tid = threadIdx.x;
    int tx = tid & 15, ty = tid >> 4;
    int rowBase = blockIdx.y * BM;
    int colBase = blockIdx.x * BN;
    int arow = tid >> 2, acol = (tid & 3) * 4;
    int brow = tid >> 4, bcol = (tid & 15) * 4;
    int ar0 = rowBase + arow, ar1 = rowBase + arow + 64;

    float4 av0 = make_float4(0.f, 0.f, 0.f, 0.f), av1 = av0;
    if (ar0 < M) av0 = *(const float4*)(A + (size_t)ar0 * K + acol);
    if (ar1 < M) av1 = *(const float4*)(A + (size_t)ar1 * K + acol);
    float4 bv = *(const float4*)(B + (size_t)brow * Ncols + colBase + bcol);
    As[0][acol + 0][arow] = av0.x; As[0][acol + 1][arow] = av0.y;
    As[0][acol + 2][arow] = av0.z; As[0][acol + 3][arow] = av0.w;
    As[0][acol + 0][arow + 64] = av1.x; As[0][acol + 1][arow + 64] = av1.y;
    As[0][acol + 2][arow + 64] = av1.z; As[0][acol + 3][arow + 64] = av1.w;
    *(float4*)&Bs[0][brow][bcol] = bv;
    __syncthreads();

    float acc[8][4] = {};
    int buf = 0;
    for (int k0 = 0; k0 < K; k0 += BK) {
        int kn = k0 + BK;
        bool has_next = kn < K;
        float4 nav0, nav1, nbv;
        if (has_next) {
            nav0 = make_float4(0.f, 0.f, 0.f, 0.f); nav1 = nav0;
            if (ar0 < M) nav0 = *(const float4*)(A + (size_t)ar0 * K + kn + acol);
            if (ar1 < M) nav1 = *(const float4*)(A + (size_t)ar1 * K + kn + acol);
            nbv = *(const float4*)(B + (size_t)(kn + brow) * Ncols + colBase + bcol);
        }
        #pragma unroll
        for (int kk = 0; kk < BK; kk++) {
            float a[8], b[4];
            #pragma unroll
            for (int i = 0; i < 8; i++) a[i] = As[buf][kk][ty * 8 + i];
            #pragma unroll
            for (int j = 0; j < 4; j++) b[j] = Bs[buf][kk][tx * 4 + j];
            #pragma unroll
            for (int i = 0; i < 8; i++)
                #pragma unroll
                for (int j = 0; j < 4; j++)
                    acc[i][j] += a[i] * b[j];
        }
        if (has_next) {
            int nb = buf ^ 1;
            As[nb][acol + 0][arow] = nav0.x; As[nb][acol + 1][arow] = nav0.y;
            As[nb][acol + 2][arow] = nav0.z; As[nb][acol + 3][arow] = nav0.w;
            As[nb][acol + 0][arow + 64] = nav1.x; As[nb][acol + 1][arow + 64] = nav1.y;
            As[nb][acol + 2][arow + 64] = nav1.z; As[nb][acol + 3][arow + 64] = nav1.w;
            *(float4*)&Bs[nb][brow][bcol] = nbv;
            __syncthreads();
            buf = nb;
        }
    }
    int cBase = colBase + tx * 4;
    float4 bb = *(const float4*)(bias + cBase);
    #pragma unroll
    for (int i = 0; i < 8; i++) {
        int r = rowBase + ty * 8 + i;
        if (r >= M) continue;
        float v0 = acc[i][0] + bb.x;
        float v1 = acc[i][1] + bb.y;
        float v2 = acc[i][2] + bb.z;
        float v3 = acc[i][3] + bb.w;
        if (act == 1) {   // elu
            v0 = elu_fast(v0); v1 = elu_fast(v1);
            v2 = elu_fast(v2); v3 = elu_fast(v3);
        }
        *(float4*)(C + (size_t)r * Ncols + cBase) = make_float4(v0, v1, v2, v3);
    }
}

// ---------------- dual-B GEMM: Cl = A@Bl + bl, Cr = A@Br + br ----------------
// Shares the A tile between both products: per kk step 16 smem operand loads
// drive 64 FFMA (4:1). K = Ncols = HID fixed. No activation (layer transforms).
__global__ void __launch_bounds__(256, 2)
k_gemm2(const float* __restrict__ A,
        const float* __restrict__ Bl, const float* __restrict__ Br,
        const float* __restrict__ bl, const float* __restrict__ br_,
        float* __restrict__ Cl, float* __restrict__ Cr, int M) {
    const int K = HID, Ncols = HID;
    __shared__ float As[2][BK][BM + 4];
    __shared__ float Bsl[2][BK][BN];
    __shared__ float Bsr[2][BK][BN];
    int tid = threadIdx.x;
    int tx = tid & 15, ty = tid >> 4;
    int rowBase = blockIdx.y * BM;
    int colBase = blockIdx.x * BN;
    int arow = tid >> 2, acol = (tid & 3) * 4;
    int brow = tid >> 4, bcol = (tid & 15) * 4;
    int ar0 = rowBase + arow, ar1 = rowBase + arow + 64;

    float4 av0 = make_float4(0.f, 0.f, 0.f, 0.f), av1 = av0;
    if (ar0 < M) av0 = *(const float4*)(A + (size_t)ar0 * K + acol);
    if (ar1 < M) av1 = *(const float4*)(A + (size_t)ar1 * K + acol);
    float4 blv = *(const float4*)(Bl + (size_t)brow * Ncols + colBase + bcol);
    float4 brv = *(const float4*)(Br + (size_t)brow * Ncols + colBase + bcol);
    As[0][acol + 0][arow] = av0.x; As[0][acol + 1][arow] = av0.y;
    As[0][acol + 2][arow] = av0.z; As[0][acol + 3][arow] = av0.w;
    As[0][acol + 0][arow + 64] = av1.x; As[0][acol + 1][arow + 64] = av1.y;
    As[0][acol + 2][arow + 64] = av1.z; As[0][acol + 3][arow + 64] = av1.w;
    *(float4*)&Bsl[0][brow][bcol] = blv;
    *(float4*)&Bsr[0][brow][bcol] = brv;
    __syncthreads();

    float accl[8][4] = {}, accr[8][4] = {};
    int buf = 0;
    for (int k0 = 0; k0 < K; k0 += BK) {
        int kn = k0 + BK;
        bool has_next = kn < K;
        float4 nav0, nav1, nblv, nbrv;
        if (has_next) {
            nav0 = make_float4(0.f, 0.f, 0.f, 0.f); nav1 = nav0;
            if (ar0 < M) nav0 = *(const float4*)(A + (size_t)ar0 * K + kn + acol);
            if (ar1 < M) nav1 = *(const float4*)(A + (size_t)ar1 * K + kn + acol);
            nblv = *(const float4*)(Bl + (size_t)(kn + brow) * Ncols + colBase + bcol);
            nbrv = *(const float4*)(Br + (size_t)(kn + brow) * Ncols + colBase + bcol);
        }
        #pragma unroll
        for (int kk = 0; kk < BK; kk++) {
            float a[8], pl[4], pr[4];
            #pragma unroll
            for (int i = 0; i < 8; i++) a[i] = As[buf][kk][ty * 8 + i];
            #pragma unroll
            for (int j = 0; j < 4; j++) pl[j] = Bsl[buf][kk][tx * 4 + j];
            #pragma unroll
            for (int j = 0; j < 4; j++) pr[j] = Bsr[buf][kk][tx * 4 + j];
            #pragma unroll
            for (int i = 0; i < 8; i++) {
                #pragma unroll
                for (int j = 0; j < 4; j++) {
                    accl[i][j] += a[i] * pl[j];
                    accr[i][j] += a[i] * pr[j];
                }
            }
        }
        if (has_next) {
            int nb = buf ^ 1;
            As[nb][acol + 0][arow] = nav0.x; As[nb][acol + 1][arow] = nav0.y;
            As[nb][acol + 2][arow] = nav0.z; As[nb][acol + 3][arow] = nav0.w;
            As[nb][acol + 0][arow + 64] = nav1.x; As[nb][acol + 1][arow + 64] = nav1.y;
            As[nb][acol + 2][arow + 64] = nav1.z; As[nb][acol + 3][arow + 64] = nav1.w;
            *(float4*)&Bsl[nb][brow][bcol] = nblv;
            *(float4*)&Bsr[nb][brow][bcol] = nbrv;
            __syncthreads();
            buf = nb;
        }
    }
    int cBase = colBase + tx * 4;
    float4 bbl = *(const float4*)(bl + cBase);
    float4 bbr = *(const float4*)(br_ + cBase);
    #pragma unroll
    for (int i = 0; i < 8; i++) {
        int r = rowBase + ty * 8 + i;
        if (r >= M) continue;
        *(float4*)(Cl + (size_t)r * Ncols + cBase) = make_float4(
            accl[i][0] + bbl.x, accl[i][1] + bbl.y,
            accl[i][2] + bbl.z, accl[i][3] + bbl.w);
        *(float4*)(Cr + (size_t)r * Ncols + cBase) = make_float4(
            accr[i][0] + bbr.x, accr[i][1] + bbr.y,
            accr[i][2] + bbr.z, accr[i][3] + bbr.w);
    }
}

// ---------------- fused GATv2 edge phase: one 128-thread block per node --------
// Online-softmax over incoming edges; each thread owns 4 channels (head=tid>>4).
// Edge p+1 prefetched before edge p's reduce/update. Self-loops => deg >= 1.
__global__ void __launch_bounds__(128)
k_fused(const float* __restrict__ xl, const float* __restrict__ xr,
        const float* __restrict__ We, const float* __restrict__ att,
        const float* __restrict__ bias, float* __restrict__ out) {
    int node = blockIdx.x;
    int tid = threadIdx.x;
    int c = tid * 4;

    float4 xrv  = *(const float4*)(xr + (size_t)node * HID + c);
    float4 wev  = *(const float4*)(We + c);
    float4 attv = *(const float4*)(att + c);

    int s0 = g_off[node], s1 = g_off[node + 1];

    float m = -1e30f, s = 0.f;
    float4 acc = make_float4(0.f, 0.f, 0.f, 0.f);

    float dv = g_cdist[s0];
    float4 xlv = *(const float4*)(xl + (size_t)g_csrc[s0] * HID + c);

    for (int p = s0; p < s1; p++) {
        float ndv = 0.f;
        float4 nxlv = make_float4(0.f, 0.f, 0.f, 0.f);
        if (p + 1 < s1) {
            ndv = g_cdist[p + 1];
            nxlv = *(const float4*)(xl + (size_t)g_csrc[p + 1] * HID + c);
        }
        float t0 = xlv.x + xrv.x + dv * wev.x;
        float t1 = xlv.y + xrv.y + dv * wev.y;
        float t2 = xlv.z + xrv.z + dv * wev.z;
        float t3 = xlv.w + xrv.w + dv * wev.w;
        t0 = t0 > 0.f ? t0 : 0.2f * t0;
        t1 = t1 > 0.f ? t1 : 0.2f * t1;
        t2 = t2 > 0.f ? t2 : 0.2f * t2;
        t3 = t3 > 0.f ? t3 : 0.2f * t3;
        float part = t0 * attv.x + t1 * attv.y + t2 * attv.z + t3 * attv.w;
        #pragma unroll
        for (int o = 8; o; o >>= 1)
            part += __shfl_xor_sync(0xFFFFFFFFu, part, o, 16);
        float newm = fmaxf(m, part);
        float eo = __expf(m - newm);       // 0 on first edge (m = -1e30)
        float en = __expf(part - newm);
        s = s * eo + en;
        acc.x = acc.x * eo + en * xlv.x;
        acc.y = acc.y * eo + en * xlv.y;
        acc.z = acc.z * eo + en * xlv.z;
        acc.w = acc.w * eo + en * xlv.w;
        m = newm;
        dv = ndv; xlv = nxlv;
    }

    float inv = 1.0f / s;
    float4 bb = *(const float4*)(bias + c);
    float r0 = elu_fast(acc.x * inv + bb.x);
    float r1 = elu_fast(acc.y * inv + bb.y);
    float r2 = elu_fast(acc.z * inv + bb.z);
    float r3 = elu_fast(acc.w * inv + bb.w);
    *(float4*)(out + (size_t)node * HID + c) = make_float4(r0, r1, r2, r3);
}

// ---------------- classifier head + log_softmax: one warp per node ----------------
__global__ void k_final(const float* __restrict__ h, const float* __restrict__ Wa,
                        const float* __restrict__ ba, float* __restrict__ out) {
    int w = (blockIdx.x * blockDim.x + threadIdx.x) >> 5;
    int lane = threadIdx.x & 31;
    if (w >= NNODES) return;
    float acc[NCLS] = {};
    const float* hr = h + (size_t)w * HID;
    for (int c = lane; c < HID; c += 32) {
        float v = hr[c];
        const float* wr = Wa + c * NCLS;
        #pragma unroll
        for (int k = 0; k < NCLS; k++) acc[k] += v * wr[k];
    }
    #pragma unroll
    for (int k = 0; k < NCLS; k++)
        #pragma unroll
        for (int o = 16; o; o >>= 1) acc[k] += __shfl_xor_sync(0xFFFFFFFFu, acc[k], o);
    if (lane == 0) {
        float m = -1e30f;
        #pragma unroll
        for (int k = 0; k < NCLS; k++) { acc[k] += ba[k]; m = fmaxf(m, acc[k]); }
        float s = 0.f;
        #pragma unroll
        for (int k = 0; k < NCLS; k++) s += expf(acc[k] - m);
        float ls = logf(s);
        #pragma unroll
        for (int k = 0; k < NCLS; k++) out[(size_t)w * NCLS + k] = acc[k] - m - ls;
    }
}

// ---------------- driver ----------------
extern "C" void kernel_launch(void* const* d_in, const int* in_sizes, int n_in,
                              void* d_out, int out_size) {
    const float* x    = (const float*)d_in[0];
    const void*  ei   = d_in[1];                 // int32 or int64, detected on device
    const float* dist = (const float*)d_in[2];
    const float* Wb   = (const float*)d_in[3];
    const float* bb   = (const float*)d_in[4];
    const float* Wl   = (const float*)d_in[5];
    const float* bl   = (const float*)d_in[6];
    const float* Wr   = (const float*)d_in[7];
    const float* br   = (const float*)d_in[8];
    const float* We   = (const float*)d_in[9];
    const float* att  = (const float*)d_in[10];
    const float* bc   = (const float*)d_in[11];
    const float* Wa   = (const float*)d_in[12];
    const float* ba   = (const float*)d_in[13];
    float* out = (float*)d_out;

    float *ph, *po, *pxl, *pxr;
    cudaGetSymbolAddress((void**)&ph,  g_h);
    cudaGetSymbolAddress((void**)&po,  g_o);
    cudaGetSymbolAddress((void**)&pxl, g_xl);
    cudaGetSymbolAddress((void**)&pxr, g_xr);

    // CSR build
    k_init<<<(NNODES + 255) / 256, 256>>>((const int*)ei);
    k_count<<<(NET + 255) / 256, 256>>>(ei);
    k_scan<<<1, 1024>>>();
    k_scatter<<<(NET + 255) / 256, 256>>>(ei, dist);

    dim3 gB(HID / BN, (NNODES + BM - 1) / BM);

    // fcnn_before: h = elu(x @ W_before + b)
    k_gemm<<<gB, 256>>>(x, Wb, bb, ph, NNODES, FIN, HID, 1);

    float* cur = ph;
    float* nxt = po;
    for (int l = 0; l < NLAY; l++) {
        k_gemm2<<<gB, 256>>>(cur,
                             Wl + (size_t)l * HID * HID, Wr + (size_t)l * HID * HID,
                             bl + l * HID, br + l * HID,
                             pxl, pxr, NNODES);
        k_fused<<<NNODES, 128>>>(pxl, pxr, We + l * HID, att + l * HID,
                                 bc + l * HID, nxt);
        float* t = cur; cur = nxt; nxt = t;
    }

    // classifier + log_softmax
    k_final<<<(NNODES * 32 + 255) / 256, 256>>>(cur, Wa, ba, out);
}